// round 5
// baseline (speedup 1.0000x reference)
#include <cuda_runtime.h>
#include <cuda_bf16.h>
#include <math.h>
#include <stdint.h>

// Problem constants (fixed by the dataset)
#define NF 100000   // firms
#define NP 500      // products
#define ED 128      // embedding dim
#define KPAD 512    // padded K / N for the big GEMM

// ---------------- scratch (static __device__ — no allocations) ----------------
__device__ __nv_bfloat16 g_tsb[(size_t)NF * KPAD];    // TS in bf16, K padded to 512, ~100 MB
__device__ float         g_tmp[NP * ED];              // E @ B           [P, D]
__device__ __nv_bfloat16 g_attb[KPAD * KPAD];         // relu(E B E^T) TRANSPOSED bf16: [n][k]
__device__ double        g_acc[2];                    // [0]=sum(max(tc-inv,0)), [1]=sum(tc)

__device__ __forceinline__ uint32_t s2u(const void* p) {
    return (uint32_t)__cvta_generic_to_shared(p);
}

// ---------------- zero scratch ----------------
__global__ void k_zero() {
    long long idx = (long long)blockIdx.x * blockDim.x + threadIdx.x;
    long long stride = (long long)gridDim.x * blockDim.x;
    uint4 z = make_uint4(0u, 0u, 0u, 0u);
    {
        long long n16 = (long long)NF * KPAD * 2 / 16;
        uint4* p = reinterpret_cast<uint4*>(g_tsb);
        for (long long i = idx; i < n16; i += stride) p[i] = z;
    }
    {
        long long n16 = (long long)KPAD * KPAD * 2 / 16;
        uint4* p = reinterpret_cast<uint4*>(g_attb);
        for (long long i = idx; i < n16; i += stride) p[i] = z;
    }
    if (idx == 0) { g_acc[0] = 0.0; g_acc[1] = 0.0; }
}

// ---- edge scatter: TSb[src, prod-NF] += max(raw_msg[:,0], 1), bf16 atomics ----
__global__ void k_scatter(const int* __restrict__ src, const int* __restrict__ prod,
                          const float* __restrict__ raw, int E) {
    int e = blockIdx.x * blockDim.x + threadIdx.x;
    if (e >= E) return;
    float a = fmaxf(raw[(size_t)e * 4], 1.0f);
    int f = src[e];
    int p = prod[e] - NF;
    size_t idx = (size_t)f * KPAD + p;
    __nv_bfloat16 hv = __float2bfloat16(a);
    __nv_bfloat16 hz = __float2bfloat16(0.f);
    __nv_bfloat162 v = (idx & 1) ? __nv_bfloat162(hz, hv) : __nv_bfloat162(hv, hz);
    atomicAdd(reinterpret_cast<__nv_bfloat162*>(&g_tsb[idx & ~(size_t)1]), v);
}

// ---------------- tmp = E @ B  ([P,D] = [P,D] x [D,D]) ----------------
__global__ void k_tmp(const float* __restrict__ E, const float* __restrict__ B) {
    __shared__ float se[ED];
    int p = blockIdx.x;
    int j = threadIdx.x;                 // 128 threads
    se[j] = E[p * ED + j];
    __syncthreads();
    float s0 = 0.f, s1 = 0.f, s2 = 0.f, s3 = 0.f;
#pragma unroll
    for (int k = 0; k < ED; k += 4) {
        s0 = fmaf(se[k + 0], B[(k + 0) * ED + j], s0);
        s1 = fmaf(se[k + 1], B[(k + 1) * ED + j], s1);
        s2 = fmaf(se[k + 2], B[(k + 2) * ED + j], s2);
        s3 = fmaf(se[k + 3], B[(k + 3) * ED + j], s3);
    }
    g_tmp[p * ED + j] = (s0 + s1) + (s2 + s3);
}

// ---------------- att_t = relu(tmp @ E^T)^T in bf16 ([n][k] layout) ----------------
__global__ void k_att(const float* __restrict__ E) {
    __shared__ float sT[16][ED + 1];
    __shared__ float sE[16][ED + 1];
    int p0 = blockIdx.y * 16, q0 = blockIdx.x * 16;
    int tid = threadIdx.x;               // 256 threads
    for (int i = tid; i < 16 * ED; i += 256) {
        int r = i / ED, c = i % ED;
        sT[r][c] = (p0 + r < NP) ? g_tmp[(p0 + r) * ED + c] : 0.f;
        sE[r][c] = (q0 + r < NP) ? E[(q0 + r) * ED + c] : 0.f;
    }
    __syncthreads();
    int tx = tid & 15, ty = tid >> 4;
    float s = 0.f;
#pragma unroll 8
    for (int k = 0; k < ED; k++) s = fmaf(sT[ty][k], sE[tx][k], s);
    int p = p0 + ty, q = q0 + tx;        // p = k index, q = n index
    if (p < NP && q < NP)
        g_attb[q * KPAD + p] = __float2bfloat16(fmaxf(s, 0.f));
}

// ---------------- main GEMM (TS @ att) on tensor cores, 3-stage cp.async ----------------
// BM=128, BN=256, BK=32, 256 threads = 8 warps (2m x 4n), warp tile 64x64.
// mma.sync.m16n8k16 bf16 -> fp32.
#define BM 128
#define BN 256
#define BK 32
#define NK (KPAD / BK)   // 16 k-steps
#define NSTG 3
#define STR 40           // smem row stride in halves (80 B: 16B-aligned, ldmatrix conflict-free)
#define A_ELEMS (BM * STR)
#define B_ELEMS (BN * STR)
#define STG_ELEMS (A_ELEMS + B_ELEMS)
#define SMEM_BYTES (NSTG * STG_ELEMS * 2)

__global__ __launch_bounds__(256) void k_gemm(const float* __restrict__ inv) {
    extern __shared__ __nv_bfloat16 sm[];
    // stage s: A at sm + s*STG_ELEMS, B at sm + s*STG_ELEMS + A_ELEMS

    const int tid  = threadIdx.x;
    const int lane = tid & 31;
    const int warp = tid >> 5;
    const int wm = warp >> 2;            // 0..1
    const int wn = warp & 3;             // 0..3
    const int m_w = wm * 64;
    const int n_w = wn * 64;
    const int bn = blockIdx.x * BN;      // x = n-tile (2): concurrent blocks share A via L2
    const int bm = blockIdx.y * BM;      // y = m-tile (782)

    const int lrow = lane & 15;          // ldmatrix row within 16x16 block
    const int lk8  = (lane >> 4) << 3;   // ldmatrix k-offset (0 or 8)

    float acc[4][8][4];
#pragma unroll
    for (int mt = 0; mt < 4; mt++)
#pragma unroll
        for (int nt = 0; nt < 8; nt++)
#pragma unroll
            for (int r = 0; r < 4; r++) acc[mt][nt][r] = 0.f;

    auto issue = [&](int stage, int k0) {
        __nv_bfloat16* As = sm + stage * STG_ELEMS;
        __nv_bfloat16* Bs = As + A_ELEMS;
        // A: 128 rows x 32 halves (64 B/row) = 512 16B chunks -> 2 per thread
#pragma unroll
        for (int p = 0; p < 2; p++) {
            int c = tid + p * 256;
            int r = c >> 2, ch = c & 3;
            long long gr = (long long)bm + r;
            const void* src = &g_tsb[(size_t)gr * KPAD + k0 + ch * 8];
            uint32_t dst = s2u(&As[r * STR + ch * 8]);
            int sz = (gr < NF) ? 16 : 0;
            asm volatile("cp.async.cg.shared.global [%0], [%1], 16, %2;\n"
                         :: "r"(dst), "l"(src), "r"(sz));
        }
        // B: 256 n-rows x 32 halves = 1024 chunks -> 4 per thread (attb fully padded)
#pragma unroll
        for (int p = 0; p < 4; p++) {
            int c = tid + p * 256;
            int r = c >> 2, ch = c & 3;
            const void* src = &g_attb[(size_t)(bn + r) * KPAD + k0 + ch * 8];
            uint32_t dst = s2u(&Bs[r * STR + ch * 8]);
            asm volatile("cp.async.cg.shared.global [%0], [%1], 16;\n"
                         :: "r"(dst), "l"(src));
        }
        asm volatile("cp.async.commit_group;\n");
    };

    issue(0, 0);
    issue(1, BK);

    for (int kt = 0; kt < NK; kt++) {
        asm volatile("cp.async.wait_group 1;\n");   // group kt complete
        __syncthreads();
        if (kt + 2 < NK) issue((kt + 2) % NSTG, (kt + 2) * BK);

        const __nv_bfloat16* Ast = sm + (kt % NSTG) * STG_ELEMS;
        const __nv_bfloat16* Bst = Ast + A_ELEMS;
#pragma unroll
        for (int ks = 0; ks < 2; ks++) {
            const int kk = ks * 16;
            // A fragments: 4 m16 tiles
            uint32_t a[4][4];
#pragma unroll
            for (int mt = 0; mt < 4; mt++) {
                uint32_t addr = s2u(&Ast[(m_w + mt * 16 + lrow) * STR + kk + lk8]);
                asm volatile("ldmatrix.sync.aligned.m8n8.x4.shared.b16 {%0,%1,%2,%3}, [%4];"
                             : "=r"(a[mt][0]), "=r"(a[mt][1]), "=r"(a[mt][2]), "=r"(a[mt][3])
                             : "r"(addr));
            }
            // B fragments: 8 n8 tiles (4 ldmatrix.x4, each covering n16)
            uint32_t b[8][2];
#pragma unroll
            for (int np = 0; np < 4; np++) {
                uint32_t addr = s2u(&Bst[(n_w + np * 16 + lrow) * STR + kk + lk8]);
                uint32_t r0, r1, r2, r3;
                asm volatile("ldmatrix.sync.aligned.m8n8.x4.shared.b16 {%0,%1,%2,%3}, [%4];"
                             : "=r"(r0), "=r"(r1), "=r"(r2), "=r"(r3)
                             : "r"(addr));
                b[np * 2][0]     = r0;
                b[np * 2 + 1][0] = r1;
                b[np * 2][1]     = r2;
                b[np * 2 + 1][1] = r3;
            }
#pragma unroll
            for (int mt = 0; mt < 4; mt++)
#pragma unroll
                for (int nt = 0; nt < 8; nt++) {
                    asm volatile(
                        "mma.sync.aligned.m16n8k16.row.col.f32.bf16.bf16.f32 "
                        "{%0,%1,%2,%3}, {%4,%5,%6,%7}, {%8,%9}, {%0,%1,%2,%3};"
                        : "+f"(acc[mt][nt][0]), "+f"(acc[mt][nt][1]),
                          "+f"(acc[mt][nt][2]), "+f"(acc[mt][nt][3])
                        : "r"(a[mt][0]), "r"(a[mt][1]), "r"(a[mt][2]), "r"(a[mt][3]),
                          "r"(b[nt][0]), "r"(b[nt][1]));
                }
        }
        __syncthreads();
    }

    // Fused epilogue: never write TC. Fragment layout: (row g, cols 2t,2t+1) and (row g+8).
    const int g = lane >> 2;
    const int t = lane & 3;
    float tD = 0.f, tC = 0.f;
#pragma unroll
    for (int mt = 0; mt < 4; mt++) {
        int r0 = bm + m_w + mt * 16 + g;
        int r1 = r0 + 8;
#pragma unroll
        for (int nt = 0; nt < 8; nt++) {
            int c0 = bn + n_w + nt * 8 + 2 * t;
            int c1 = c0 + 1;
            if (r0 < NF) {
                if (c0 < NP) {
                    float v = acc[mt][nt][0];
                    tC += v; tD += fmaxf(v - inv[(size_t)r0 * NP + c0], 0.f);
                }
                if (c1 < NP) {
                    float v = acc[mt][nt][1];
                    tC += v; tD += fmaxf(v - inv[(size_t)r0 * NP + c1], 0.f);
                }
            }
            if (r1 < NF) {
                if (c0 < NP) {
                    float v = acc[mt][nt][2];
                    tC += v; tD += fmaxf(v - inv[(size_t)r1 * NP + c0], 0.f);
                }
                if (c1 < NP) {
                    float v = acc[mt][nt][3];
                    tC += v; tD += fmaxf(v - inv[(size_t)r1 * NP + c1], 0.f);
                }
            }
        }
    }

    // block reduction in double, one atomic pair per block
    double dD = (double)tD, dC = (double)tC;
#pragma unroll
    for (int off = 16; off > 0; off >>= 1) {
        dD += __shfl_down_sync(0xFFFFFFFFu, dD, off);
        dC += __shfl_down_sync(0xFFFFFFFFu, dC, off);
    }
    __shared__ double sD[8], sC[8];
    if (lane == 0) { sD[warp] = dD; sC[warp] = dC; }
    __syncthreads();
    if (warp == 0) {
        double rD = (lane < 8) ? sD[lane] : 0.0;
        double rC = (lane < 8) ? sC[lane] : 0.0;
#pragma unroll
        for (int off = 4; off > 0; off >>= 1) {
            rD += __shfl_down_sync(0xFFFFFFFFu, rD, off);
            rC += __shfl_down_sync(0xFFFFFFFFu, rC, off);
        }
        if (lane == 0) {
            atomicAdd(&g_acc[0], rD);
            atomicAdd(&g_acc[1], rC);
        }
    }
}

// ---------------- finalize: 3 scalars ----------------
__global__ void k_fin(float* __restrict__ out, int E) {
    double D = g_acc[0] * 10.0;   // DEBT_PENALTY
    double C = g_acc[1];          // CONSUMPTION_REWARD = 1
    double n = (double)E;
    out[0] = (float)((D - C) / n);
    out[1] = (float)(D / n);
    out[2] = (float)(C / n);
}

// ---------------- launch ----------------
extern "C" void kernel_launch(void* const* d_in, const int* in_sizes, int n_in,
                              void* d_out, int out_size) {
    const int*   src  = (const int*)d_in[0];
    // d_in[1] = dst — unused by the reference
    const int*   prod = (const int*)d_in[2];
    const float* raw  = (const float*)d_in[3];
    const float* emb  = (const float*)d_in[4];
    const float* bil  = (const float*)d_in[5];
    const float* inv  = (const float*)d_in[6];
    float* out = (float*)d_out;
    int E = in_sizes[0];

    // idempotent, non-stream API: safe on every call (incl. under graph capture)
    cudaFuncSetAttribute(k_gemm, cudaFuncAttributeMaxDynamicSharedMemorySize, SMEM_BYTES);

    k_zero<<<4096, 256>>>();
    k_scatter<<<(E + 255) / 256, 256>>>(src, prod, raw, E);
    k_tmp<<<NP, ED>>>(emb, bil);
    k_att<<<dim3((KPAD + 15) / 16, (KPAD + 15) / 16), 256>>>(emb);
    k_gemm<<<dim3(KPAD / BN, (NF + BM - 1) / BM), 256, SMEM_BYTES>>>(inv);
    k_fin<<<1, 1>>>(out, E);
}

// round 6
// speedup vs baseline: 1.4502x; 1.4502x over previous
#include <cuda_runtime.h>
#include <cuda_bf16.h>
#include <math.h>
#include <stdint.h>

// Problem constants (fixed by the dataset)
#define NF 100000   // firms
#define NP 500      // products
#define ED 128      // embedding dim
#define KPAD 512    // padded K / N for the big GEMM

// ---------------- scratch (static __device__ — no allocations) ----------------
__device__ __nv_bfloat16 g_tsb[(size_t)NF * KPAD];    // TS in bf16, K padded to 512, ~100 MB
__device__ float         g_tmp[NP * ED];              // E @ B           [P, D]
__device__ __nv_bfloat16 g_attb[KPAD * KPAD];         // relu(E B E^T) TRANSPOSED bf16: [n][k]
__device__ double        g_acc[2];                    // [0]=sum(max(tc-inv,0)), [1]=sum(tc)

__device__ __forceinline__ uint32_t s2u(const void* p) {
    return (uint32_t)__cvta_generic_to_shared(p);
}

// ---------------- zero scratch ----------------
__global__ void k_zero() {
    long long idx = (long long)blockIdx.x * blockDim.x + threadIdx.x;
    long long stride = (long long)gridDim.x * blockDim.x;
    uint4 z = make_uint4(0u, 0u, 0u, 0u);
    {
        long long n16 = (long long)NF * KPAD * 2 / 16;
        uint4* p = reinterpret_cast<uint4*>(g_tsb);
        for (long long i = idx; i < n16; i += stride) p[i] = z;
    }
    {
        long long n16 = (long long)KPAD * KPAD * 2 / 16;
        uint4* p = reinterpret_cast<uint4*>(g_attb);
        for (long long i = idx; i < n16; i += stride) p[i] = z;
    }
    if (idx == 0) { g_acc[0] = 0.0; g_acc[1] = 0.0; }
}

// ---- edge scatter: TSb[src, prod-NF] += max(raw_msg[:,0], 1), bf16 atomics ----
__global__ void k_scatter(const int* __restrict__ src, const int* __restrict__ prod,
                          const float* __restrict__ raw, int E) {
    int e = blockIdx.x * blockDim.x + threadIdx.x;
    if (e >= E) return;
    float a = fmaxf(raw[(size_t)e * 4], 1.0f);
    int f = src[e];
    int p = prod[e] - NF;
    size_t idx = (size_t)f * KPAD + p;
    __nv_bfloat16 hv = __float2bfloat16(a);
    __nv_bfloat16 hz = __float2bfloat16(0.f);
    __nv_bfloat162 v = (idx & 1) ? __nv_bfloat162(hz, hv) : __nv_bfloat162(hv, hz);
    atomicAdd(reinterpret_cast<__nv_bfloat162*>(&g_tsb[idx & ~(size_t)1]), v);
}

// ---------------- tmp = E @ B  ([P,D] = [P,D] x [D,D]) ----------------
__global__ void k_tmp(const float* __restrict__ E, const float* __restrict__ B) {
    __shared__ float se[ED];
    int p = blockIdx.x;
    int j = threadIdx.x;                 // 128 threads
    se[j] = E[p * ED + j];
    __syncthreads();
    float s0 = 0.f, s1 = 0.f, s2 = 0.f, s3 = 0.f;
#pragma unroll
    for (int k = 0; k < ED; k += 4) {
        s0 = fmaf(se[k + 0], B[(k + 0) * ED + j], s0);
        s1 = fmaf(se[k + 1], B[(k + 1) * ED + j], s1);
        s2 = fmaf(se[k + 2], B[(k + 2) * ED + j], s2);
        s3 = fmaf(se[k + 3], B[(k + 3) * ED + j], s3);
    }
    g_tmp[p * ED + j] = (s0 + s1) + (s2 + s3);
}

// ---------------- att_t = relu(tmp @ E^T)^T in bf16 ([n][k] layout) ----------------
__global__ void k_att(const float* __restrict__ E) {
    __shared__ float sT[16][ED + 1];
    __shared__ float sE[16][ED + 1];
    int p0 = blockIdx.y * 16, q0 = blockIdx.x * 16;
    int tid = threadIdx.x;               // 256 threads
    for (int i = tid; i < 16 * ED; i += 256) {
        int r = i / ED, c = i % ED;
        sT[r][c] = (p0 + r < NP) ? g_tmp[(p0 + r) * ED + c] : 0.f;
        sE[r][c] = (q0 + r < NP) ? E[(q0 + r) * ED + c] : 0.f;
    }
    __syncthreads();
    int tx = tid & 15, ty = tid >> 4;
    float s = 0.f;
#pragma unroll 8
    for (int k = 0; k < ED; k++) s = fmaf(sT[ty][k], sE[tx][k], s);
    int p = p0 + ty, q = q0 + tx;        // p = k index, q = n index
    if (p < NP && q < NP)
        g_attb[q * KPAD + p] = __float2bfloat16(fmaxf(s, 0.f));
}

// ---------------- main GEMM (TS @ att) on tensor cores, 3-stage cp.async ----------------
// BM=128, BN=128, BK=32, 256 threads = 8 warps (4m x 2n), warp tile 32x64.
// mma.sync.m16n8k16 bf16 -> fp32.  (identical compute shape to the 469us kernel;
// ONLY the pipeline depth changed: 2-stage/wait0 -> 3-stage/wait1)
#define BM 128
#define BN 128
#define BK 32
#define NK (KPAD / BK)   // 16 k-steps
#define NSTG 3
#define STR 40           // smem row stride in halves (80 B: 16B-aligned, ldmatrix conflict-free)
#define A_ELEMS (BM * STR)
#define B_ELEMS (BN * STR)
#define STG_ELEMS (A_ELEMS + B_ELEMS)
#define SMEM_BYTES (NSTG * STG_ELEMS * 2)   // 61440 B -> 2 CTAs/SM

__global__ __launch_bounds__(256) void k_gemm(const float* __restrict__ inv) {
    extern __shared__ __nv_bfloat16 sm[];

    const int tid  = threadIdx.x;
    const int lane = tid & 31;
    const int warp = tid >> 5;
    const int wm = warp >> 1;            // 0..3
    const int wn = warp & 1;             // 0..1
    const int m_w = wm * 32;
    const int n_w = wn * 64;
    const int bn = blockIdx.x * BN;      // x = n-tile (4): concurrent blocks share A via L2
    const int bm = blockIdx.y * BM;      // y = m-tile (782)

    const int lrow = lane & 15;          // ldmatrix row within 16x16 block
    const int lk8  = (lane >> 4) << 3;   // ldmatrix k-offset (0 or 8)

    float acc[2][8][4];
#pragma unroll
    for (int mt = 0; mt < 2; mt++)
#pragma unroll
        for (int nt = 0; nt < 8; nt++)
#pragma unroll
            for (int r = 0; r < 4; r++) acc[mt][nt][r] = 0.f;

    auto issue = [&](int stage, int k0) {
        __nv_bfloat16* As = sm + stage * STG_ELEMS;
        __nv_bfloat16* Bs = As + A_ELEMS;
#pragma unroll
        for (int p = 0; p < 2; p++) {
            int c = tid + p * 256;
            int r = c >> 2, ch = c & 3;
            long long gr = (long long)bm + r;
            const void* src = &g_tsb[(size_t)gr * KPAD + k0 + ch * 8];
            uint32_t dst = s2u(&As[r * STR + ch * 8]);
            int sz = (gr < NF) ? 16 : 0;
            asm volatile("cp.async.cg.shared.global [%0], [%1], 16, %2;\n"
                         :: "r"(dst), "l"(src), "r"(sz));
        }
#pragma unroll
        for (int p = 0; p < 2; p++) {
            int c = tid + p * 256;
            int r = c >> 2, ch = c & 3;
            const void* src = &g_attb[(size_t)(bn + r) * KPAD + k0 + ch * 8];
            uint32_t dst = s2u(&Bs[r * STR + ch * 8]);
            asm volatile("cp.async.cg.shared.global [%0], [%1], 16;\n"
                         :: "r"(dst), "l"(src));
        }
        asm volatile("cp.async.commit_group;\n");
    };

    issue(0, 0);
    issue(1, BK);

    for (int kt = 0; kt < NK; kt++) {
        asm volatile("cp.async.wait_group 1;\n");   // stage kt resident; kt+1 may be in flight
        __syncthreads();
        if (kt + 2 < NK) issue((kt + 2) % NSTG, (kt + 2) * BK);

        const __nv_bfloat16* Ast = sm + (kt % NSTG) * STG_ELEMS;
        const __nv_bfloat16* Bst = Ast + A_ELEMS;
#pragma unroll
        for (int ks = 0; ks < 2; ks++) {
            const int kk = ks * 16;
            uint32_t a[2][4];
#pragma unroll
            for (int mt = 0; mt < 2; mt++) {
                uint32_t addr = s2u(&Ast[(m_w + mt * 16 + lrow) * STR + kk + lk8]);
                asm volatile("ldmatrix.sync.aligned.m8n8.x4.shared.b16 {%0,%1,%2,%3}, [%4];"
                             : "=r"(a[mt][0]), "=r"(a[mt][1]), "=r"(a[mt][2]), "=r"(a[mt][3])
                             : "r"(addr));
            }
            uint32_t b[8][2];
#pragma unroll
            for (int np = 0; np < 4; np++) {
                uint32_t addr = s2u(&Bst[(n_w + np * 16 + lrow) * STR + kk + lk8]);
                uint32_t r0, r1, r2, r3;
                asm volatile("ldmatrix.sync.aligned.m8n8.x4.shared.b16 {%0,%1,%2,%3}, [%4];"
                             : "=r"(r0), "=r"(r1), "=r"(r2), "=r"(r3)
                             : "r"(addr));
                b[np * 2][0]     = r0;
                b[np * 2 + 1][0] = r1;
                b[np * 2][1]     = r2;
                b[np * 2 + 1][1] = r3;
            }
#pragma unroll
            for (int mt = 0; mt < 2; mt++)
#pragma unroll
                for (int nt = 0; nt < 8; nt++) {
                    asm volatile(
                        "mma.sync.aligned.m16n8k16.row.col.f32.bf16.bf16.f32 "
                        "{%0,%1,%2,%3}, {%4,%5,%6,%7}, {%8,%9}, {%0,%1,%2,%3};"
                        : "+f"(acc[mt][nt][0]), "+f"(acc[mt][nt][1]),
                          "+f"(acc[mt][nt][2]), "+f"(acc[mt][nt][3])
                        : "r"(a[mt][0]), "r"(a[mt][1]), "r"(a[mt][2]), "r"(a[mt][3]),
                          "r"(b[nt][0]), "r"(b[nt][1]));
                }
        }
        __syncthreads();   // protect stage kt%3 before it is re-issued at kt+2
    }

    // Fused epilogue: never write TC.
    const int g = lane >> 2;
    const int t = lane & 3;
    float tD = 0.f, tC = 0.f;
#pragma unroll
    for (int mt = 0; mt < 2; mt++) {
        int r0 = bm + m_w + mt * 16 + g;
        int r1 = r0 + 8;
#pragma unroll
        for (int nt = 0; nt < 8; nt++) {
            int c0 = bn + n_w + nt * 8 + 2 * t;
            int c1 = c0 + 1;
            if (r0 < NF) {
                if (c0 < NP) {
                    float v = acc[mt][nt][0];
                    tC += v; tD += fmaxf(v - inv[(size_t)r0 * NP + c0], 0.f);
                }
                if (c1 < NP) {
                    float v = acc[mt][nt][1];
                    tC += v; tD += fmaxf(v - inv[(size_t)r0 * NP + c1], 0.f);
                }
            }
            if (r1 < NF) {
                if (c0 < NP) {
                    float v = acc[mt][nt][2];
                    tC += v; tD += fmaxf(v - inv[(size_t)r1 * NP + c0], 0.f);
                }
                if (c1 < NP) {
                    float v = acc[mt][nt][3];
                    tC += v; tD += fmaxf(v - inv[(size_t)r1 * NP + c1], 0.f);
                }
            }
        }
    }

    // block reduction in double, one atomic pair per block
    double dD = (double)tD, dC = (double)tC;
#pragma unroll
    for (int off = 16; off > 0; off >>= 1) {
        dD += __shfl_down_sync(0xFFFFFFFFu, dD, off);
        dC += __shfl_down_sync(0xFFFFFFFFu, dC, off);
    }
    __shared__ double sD[8], sC[8];
    if (lane == 0) { sD[warp] = dD; sC[warp] = dC; }
    __syncthreads();
    if (warp == 0) {
        double rD = (lane < 8) ? sD[lane] : 0.0;
        double rC = (lane < 8) ? sC[lane] : 0.0;
#pragma unroll
        for (int off = 4; off > 0; off >>= 1) {
            rD += __shfl_down_sync(0xFFFFFFFFu, rD, off);
            rC += __shfl_down_sync(0xFFFFFFFFu, rC, off);
        }
        if (lane == 0) {
            atomicAdd(&g_acc[0], rD);
            atomicAdd(&g_acc[1], rC);
        }
    }
}

// ---------------- finalize: 3 scalars ----------------
__global__ void k_fin(float* __restrict__ out, int E) {
    double D = g_acc[0] * 10.0;   // DEBT_PENALTY
    double C = g_acc[1];          // CONSUMPTION_REWARD = 1
    double n = (double)E;
    out[0] = (float)((D - C) / n);
    out[1] = (float)(D / n);
    out[2] = (float)(C / n);
}

// ---------------- launch ----------------
extern "C" void kernel_launch(void* const* d_in, const int* in_sizes, int n_in,
                              void* d_out, int out_size) {
    const int*   src  = (const int*)d_in[0];
    // d_in[1] = dst — unused by the reference
    const int*   prod = (const int*)d_in[2];
    const float* raw  = (const float*)d_in[3];
    const float* emb  = (const float*)d_in[4];
    const float* bil  = (const float*)d_in[5];
    const float* inv  = (const float*)d_in[6];
    float* out = (float*)d_out;
    int E = in_sizes[0];

    // idempotent, non-stream API: safe on every call (incl. under graph capture)
    cudaFuncSetAttribute(k_gemm, cudaFuncAttributeMaxDynamicSharedMemorySize, SMEM_BYTES);

    k_zero<<<4096, 256>>>();
    k_scatter<<<(E + 255) / 256, 256>>>(src, prod, raw, E);
    k_tmp<<<NP, ED>>>(emb, bil);
    k_att<<<dim3((KPAD + 15) / 16, (KPAD + 15) / 16), 256>>>(emb);
    k_gemm<<<dim3(KPAD / BN, (NF + BM - 1) / BM), 256, SMEM_BYTES>>>(inv);
    k_fin<<<1, 1>>>(out, E);
}